// round 15
// baseline (speedup 1.0000x reference)
#include <cuda_runtime.h>
#include <cuda_bf16.h>
#include <math.h>
#include <cstdint>

// Problem dims
#define Bx 4
#define Nx 2048
#define Dx 512
#define Hx 8
#define Ox 64
#define ROWS (Bx*Nx)      // 8192
#define QKVCOLS (Hx*Ox*3) // 1536

// d_out packing: out (B,N,64) | next_mem (B,H,64,64) | next_z (B,H,64)
#define OUT_MEM_OFF (ROWS*Ox)
#define OUT_Z_OFF   (OUT_MEM_OFF + Bx*Hx*Ox*Ox)

// Scratch
__device__ float    g_pe[Nx*Dx];
__device__ uint32_t g_xh2[ROWS*Dx/2];
__device__ uint32_t g_xl2[ROWS*Dx/2];
__device__ uint32_t g_Wth2[QKVCOLS*Dx/2];
__device__ uint32_t g_Wtl2[QKVCOLS*Dx/2];
__device__ float g_q[ROWS*Dx];
__device__ float g_k[ROWS*Dx];
__device__ float g_v[ROWS*Dx];
__device__ uint32_t g_kh2[ROWS*Dx/2];
__device__ uint32_t g_kl2[ROWS*Dx/2];
__device__ float g_vt[ROWS*Dx];
__device__ float g_Amem[ROWS*Dx];
__device__ float g_A[ROWS*Dx];
__device__ uint32_t g_Wph2[Ox*Dx/2];   // Wp^T [o][kpair] bf16x2 hi
__device__ uint32_t g_Wpl2[Ox*Dx/2];   // lo
__device__ float g_part[32*8*Ox*Ox];
__device__ float g_zpart[32*8*Ox];

struct TSArr { float v[Dx]; };

// Side stream + fork/join events, created once at static init.
struct SideStream {
    cudaStream_t s;
    cudaEvent_t e_fork, e_join;
    SideStream() {
        cudaStreamCreateWithFlags(&s, cudaStreamNonBlocking);
        cudaEventCreateWithFlags(&e_fork, cudaEventDisableTiming);
        cudaEventCreateWithFlags(&e_join, cudaEventDisableTiming);
    }
};
static SideStream g_ss;

// ---------------------------------------------------------------------------
// helpers (plain sm_80+ PTX)
// ---------------------------------------------------------------------------
__device__ __forceinline__ uint32_t f2tf32(float x) {
    uint32_t r;
    asm("cvt.rna.tf32.f32 %0, %1;" : "=r"(r) : "f"(x));
    return r;
}
__device__ __forceinline__ void mma_tf32(float* c, const uint32_t* a, const uint32_t* b) {
    asm volatile("mma.sync.aligned.m16n8k8.row.col.f32.tf32.tf32.f32 "
        "{%0,%1,%2,%3}, {%4,%5,%6,%7}, {%8,%9}, {%0,%1,%2,%3};"
        : "+f"(c[0]), "+f"(c[1]), "+f"(c[2]), "+f"(c[3])
        : "r"(a[0]), "r"(a[1]), "r"(a[2]), "r"(a[3]), "r"(b[0]), "r"(b[1]));
}
__device__ __forceinline__ void mma_bf16(float* c, const uint32_t* a, const uint32_t* b) {
    asm volatile("mma.sync.aligned.m16n8k16.row.col.f32.bf16.bf16.f32 "
        "{%0,%1,%2,%3}, {%4,%5,%6,%7}, {%8,%9}, {%0,%1,%2,%3};"
        : "+f"(c[0]), "+f"(c[1]), "+f"(c[2]), "+f"(c[3])
        : "r"(a[0]), "r"(a[1]), "r"(a[2]), "r"(a[3]), "r"(b[0]), "r"(b[1]));
}
__device__ __forceinline__ uint32_t pack_bf16x2(float e0, float e1) {
    uint32_t d;
    asm("cvt.rn.bf16x2.f32 %0, %1, %2;" : "=r"(d) : "f"(e1), "f"(e0));
    return d;
}
__device__ __forceinline__ float bf16hi_f(float x) {
    return __bfloat162float(__float2bfloat16(x));
}
__device__ __forceinline__ float2 unpack_bf16x2(uint32_t w) {
    __nv_bfloat162 b = *(__nv_bfloat162*)&w;
    return make_float2(__bfloat162float(b.x), __bfloat162float(b.y));
}
__device__ __forceinline__ uint32_t smem_u32(const void* p) {
    uint32_t a;
    asm("{ .reg .u64 t; cvta.to.shared.u64 t, %1; cvt.u32.u64 %0, t; }" : "=r"(a) : "l"(p));
    return a;
}
__device__ __forceinline__ void cp16(uint32_t dst, const void* src) {
    asm volatile("cp.async.ca.shared.global [%0], [%1], 16;" :: "r"(dst), "l"(src));
}
__device__ __forceinline__ void cp_commit() { asm volatile("cp.async.commit_group;" ::: "memory"); }
template<int N> __device__ __forceinline__ void cp_wait() {
    asm volatile("cp.async.wait_group %0;" :: "n"(N) : "memory");
}

// ---------------------------------------------------------------------------
// Kernel 0: merged prep = PE table | W transpose+split | Wp^T pack hi/lo
// ---------------------------------------------------------------------------
#define PE_BLOCKS 4096
#define WT_BLOCKS 768
#define PW_BLOCKS 64
__global__ __launch_bounds__(256) void prep_kernel(TSArr ts,
                                                   const float* __restrict__ wk,
                                                   const float* __restrict__ wo) {
    __shared__ float t[32][33];
    int bid = blockIdx.x;
    if (bid < PE_BLOCKS) {
        int idx = bid*256 + threadIdx.x;
        int i = idx & (Dx-1);
        int n = idx >> 9;
        float ang = (float)n * ts.v[i];
        const float C1 = 6.28125f;
        const float C2 = (float)(6.283185307179586 - 6.28125);
        const float C3 = (float)(6.283185307179586 - 6.28125
                                 - (double)(float)(6.283185307179586 - 6.28125));
        float k = rintf(ang * 0.15915494309189535f);
        float r = fmaf(-k, C1, ang);
        r = fmaf(-k, C2, r);
        r = fmaf(-k, C3, r);
        g_pe[idx] = (i & 1) ? cosf(r) : sinf(r);
    } else if (bid < PE_BLOCKS + WT_BLOCKS) {
        int wtb = bid - PE_BLOCKS;
        const int colBase = (wtb % 48)*32;
        const int kBase   = (wtb / 48)*32;
        const int tx = threadIdx.x & 31, ty = threadIdx.x >> 5;
        #pragma unroll
        for (int j = ty; j < 32; j += 8)
            t[j][tx] = wk[(size_t)(kBase + j)*QKVCOLS + colBase + tx];
        __syncthreads();
        #pragma unroll
        for (int it = 0; it < 2; it++) {
            int e = threadIdx.x + 256*it;
            int j = e >> 4;
            int p = e & 15;
            int col  = colBase + j;
            int orow = (col % 3)*512 + col/3;
            float w0 = t[2*p][j],  w1 = t[2*p+1][j];
            float h0 = bf16hi_f(w0), h1 = bf16hi_f(w1);
            size_t o = (size_t)orow*(Dx/2) + (kBase>>1) + p;
            g_Wth2[o] = pack_bf16x2(h0, h1);
            g_Wtl2[o] = pack_bf16x2(w0 - h0, w1 - h1);
        }
    } else {
        // Wp^T pack: Wpt[o][k] = wo[(i*8 + h)*64 + o], k = h*64+i, kpair p
        int e = (bid - PE_BLOCKS - WT_BLOCKS)*256 + threadIdx.x;   // 0..16383
        int o = e >> 8;
        int p = e & 255;
        int k0 = 2*p, k1 = 2*p + 1;
        float w0 = wo[((k0 & 63)*Hx + (k0 >> 6))*Ox + o];
        float w1 = wo[((k1 & 63)*Hx + (k1 >> 6))*Ox + o];
        float h0 = bf16hi_f(w0), h1 = bf16hi_f(w1);
        g_Wph2[o*(Dx/2) + p] = pack_bf16x2(h0, h1);
        g_Wpl2[o*(Dx/2) + p] = pack_bf16x2(w0 - h0, w1 - h1);
    }
}

// ---------------------------------------------------------------------------
// Kernel 0c: x = in + pe, bf16 hi/lo split, kpair-packed
// ---------------------------------------------------------------------------
__global__ void xsplit_kernel(const float* __restrict__ in) {
    int t8 = blockIdx.x * blockDim.x + threadIdx.x;
    if (t8 >= ROWS*Dx/8) return;
    int idx = t8 << 3;
    int i = idx & (Dx-1);
    int row = idx >> 9;
    int n = row & (Nx-1);
    uint32_t hw[4], lw[4];
    #pragma unroll
    for (int half = 0; half < 2; half++) {
        float4 xa = *(const float4*)&in[idx + 4*half];
        float4 pe = *(const float4*)&g_pe[(n<<9) + i + 4*half];
        float v[4] = {xa.x+pe.x, xa.y+pe.y, xa.z+pe.z, xa.w+pe.w};
        float h0 = bf16hi_f(v[0]), h1 = bf16hi_f(v[1]);
        float h2 = bf16hi_f(v[2]), h3 = bf16hi_f(v[3]);
        hw[2*half]   = pack_bf16x2(h0, h1);
        hw[2*half+1] = pack_bf16x2(h2, h3);
        lw[2*half]   = pack_bf16x2(v[0]-h0, v[1]-h1);
        lw[2*half+1] = pack_bf16x2(v[2]-h2, v[3]-h3);
    }
    *(uint4*)&g_xh2[idx>>1] = make_uint4(hw[0],hw[1],hw[2],hw[3]);
    *(uint4*)&g_xl2[idx>>1] = make_uint4(lw[0],lw[1],lw[2],lw[3]);
}

// ---------------------------------------------------------------------------
// Kernel 1: bf16 m16n8k16 hi/lo 3-pass QKV GEMM, cp.async double-buffered.
// ---------------------------------------------------------------------------
#define TWB 16
#define TILE_WORDS_B (128*TWB)
#define QKV_SMEM_BYTES (8*TILE_WORDS_B*4)    // 65536

__device__ __forceinline__ int swzb(int r, int c) { return r*TWB + (c ^ (((r>>1)&3)<<2)); }

__global__ __launch_bounds__(512) void gemm_qkv_mma(int dummy) {
    extern __shared__ uint32_t sm[];
    const uint32_t sbase = smem_u32(sm);
    const int tid  = threadIdx.x;
    const int warp = tid >> 5;
    const int lane = tid & 31;
    const int wm = warp >> 2;
    const int wn = warp & 3;
    const int bm = blockIdx.y * 128;
    const int bn = blockIdx.x * 128;
    const int g = lane >> 2;
    const int q = lane & 3;

    float acc[2][4][4] = {};

    auto load_chunk = [&](int s, int buf) {
        #pragma unroll
        for (int t = 0; t < 4; t++) {
            const uint32_t* src = (t==0) ? g_xh2 : (t==1) ? g_xl2 : (t==2) ? g_Wth2 : g_Wtl2;
            const int rowbase = (t < 2) ? bm : bn;
            int r = tid >> 2, cg = (tid & 3) << 2;
            uint32_t dst = sbase + (uint32_t)(((buf*4 + t)*TILE_WORDS_B + swzb(r, cg)) << 2);
            cp16(dst, src + (size_t)(rowbase + r)*(Dx/2) + s*TWB + cg);
        }
    };

    load_chunk(0, 0);
    cp_commit();

    for (int s = 0; s < 16; s++) {
        const int buf = s & 1;
        if (s + 1 < 16) {
            load_chunk(s+1, buf ^ 1);
            cp_commit();
            cp_wait<1>();
        } else {
            cp_wait<0>();
        }
        __syncthreads();

        const uint32_t* Xh = sm + (buf*4 + 0)*TILE_WORDS_B;
        const uint32_t* Xl = sm + (buf*4 + 1)*TILE_WORDS_B;
        const uint32_t* Wh = sm + (buf*4 + 2)*TILE_WORDS_B;
        const uint32_t* Wl = sm + (buf*4 + 3)*TILE_WORDS_B;

        #pragma unroll
        for (int ks = 0; ks < 2; ks++) {
            const int kb = ks*8;
            uint32_t ah[2][4], al[2][4], bh[4][2], bl[4][2];
            #pragma unroll
            for (int mf = 0; mf < 2; mf++) {
                int r0 = wm*32 + mf*16 + g;
                ah[mf][0] = Xh[swzb(r0,   kb+q)];
                ah[mf][1] = Xh[swzb(r0+8, kb+q)];
                ah[mf][2] = Xh[swzb(r0,   kb+q+4)];
                ah[mf][3] = Xh[swzb(r0+8, kb+q+4)];
                al[mf][0] = Xl[swzb(r0,   kb+q)];
                al[mf][1] = Xl[swzb(r0+8, kb+q)];
                al[mf][2] = Xl[swzb(r0,   kb+q+4)];
                al[mf][3] = Xl[swzb(r0+8, kb+q+4)];
            }
            #pragma unroll
            for (int nf = 0; nf < 4; nf++) {
                int nc = wn*32 + nf*8 + g;
                bh[nf][0] = Wh[swzb(nc, kb+q)];
                bh[nf][1] = Wh[swzb(nc, kb+q+4)];
                bl[nf][0] = Wl[swzb(nc, kb+q)];
                bl[nf][1] = Wl[swzb(nc, kb+q+4)];
            }
            #pragma unroll
            for (int mf = 0; mf < 2; mf++)
                #pragma unroll
                for (int nf = 0; nf < 4; nf++) {
                    mma_bf16(acc[mf][nf], ah[mf], bh[nf]);
                    mma_bf16(acc[mf][nf], ah[mf], bl[nf]);
                    mma_bf16(acc[mf][nf], al[mf], bh[nf]);
                }
        }
        __syncthreads();
    }

    const int sec = bn >> 9;
    const int nb  = bn & 511;
    #pragma unroll
    for (int mf = 0; mf < 2; mf++) {
        int m = bm + wm*32 + mf*16 + g;
        #pragma unroll
        for (int nf = 0; nf < 4; nf++) {
            int col = nb + wn*32 + nf*8 + q*2;
            float a0 = acc[mf][nf][0], a1 = acc[mf][nf][1];
            float a2 = acc[mf][nf][2], a3 = acc[mf][nf][3];
            if (sec == 0) {
                *(float2*)&g_k[(size_t)m*Dx + col]     = make_float2(a0, a1);
                *(float2*)&g_k[(size_t)(m+8)*Dx + col] = make_float2(a2, a3);
                float h0 = bf16hi_f(a0), h1 = bf16hi_f(a1);
                float h2 = bf16hi_f(a2), h3 = bf16hi_f(a3);
                int wc = col >> 1;
                g_kh2[(size_t)m*(Dx/2) + wc]     = pack_bf16x2(h0, h1);
                g_kl2[(size_t)m*(Dx/2) + wc]     = pack_bf16x2(a0-h0, a1-h1);
                g_kh2[(size_t)(m+8)*(Dx/2) + wc] = pack_bf16x2(h2, h3);
                g_kl2[(size_t)(m+8)*(Dx/2) + wc] = pack_bf16x2(a2-h2, a3-h3);
            } else if (sec == 1) {
                *(float2*)&g_v[(size_t)m*Dx + col]     = make_float2(a0, a1);
                *(float2*)&g_v[(size_t)(m+8)*Dx + col] = make_float2(a2, a3);
                *(float2*)&g_vt[(size_t)m*Dx + col] =
                    make_float2(__uint_as_float(f2tf32(a0)), __uint_as_float(f2tf32(a1)));
                *(float2*)&g_vt[(size_t)(m+8)*Dx + col] =
                    make_float2(__uint_as_float(f2tf32(a2)), __uint_as_float(f2tf32(a3)));
            } else {
                *(float2*)&g_q[(size_t)m*Dx + col]     = make_float2(a0, a1);
                *(float2*)&g_q[(size_t)(m+8)*Dx + col] = make_float2(a2, a3);
            }
        }
    }
}

// ---------------------------------------------------------------------------
// Kernel 2: causal flash attention (R12/R14 version, unchanged)
// ---------------------------------------------------------------------------
#define FST 68
#define KROW 36
#define KMAT (64*KROW)
#define KSET (2*KMAT)
#define VOFF (2*KSET)
#define POFF (VOFF + 64*FST)
#define FLASH_SMEM ((POFF + 4*16*FST)*4)   // 71680 B

__global__ __launch_bounds__(128, 3) void flash_mma() {
    extern __shared__ uint32_t fsm[];
    const uint32_t sbase = smem_u32(fsm);
    float* Vs = (float*)(fsm + VOFF);
    const int bh = blockIdx.y;
    const int b = bh >> 3, h = bh & 7;
    const int qt = gridDim.x - 1 - blockIdx.x;
    const int tid = threadIdx.x, warp = tid >> 5, lane = tid & 31;
    const int g = lane >> 2, qd = lane & 3;
    float* Pw = (float*)(fsm + POFF) + warp*16*FST;

    const float SC = 0.04419417382415922f;

    auto load_K = [&](int kt, int buf) {
        const uint32_t* srch = g_kh2 + ((size_t)(b*Nx + kt*64))*(Dx/2) + h*32;
        const uint32_t* srcl = g_kl2 + ((size_t)(b*Nx + kt*64))*(Dx/2) + h*32;
        #pragma unroll
        for (int ii = 0; ii < 4; ii++) {
            int f = tid + 128*ii;
            int r = f >> 3, c4 = (f & 7) << 2;
            cp16(sbase + (uint32_t)((buf*KSET + r*KROW + c4) << 2),
                 srch + (size_t)r*(Dx/2) + c4);
            cp16(sbase + (uint32_t)((buf*KSET + KMAT + r*KROW + c4) << 2),
                 srcl + (size_t)r*(Dx/2) + c4);
        }
    };
    auto load_V = [&](int kt) {
        const float* srcv = g_vt + ((size_t)(b*Nx + kt*64))*Dx + h*64;
        #pragma unroll
        for (int ii = 0; ii < 8; ii++) {
            int f = tid + 128*ii;
            int r = f >> 4, c4 = (f & 15) << 2;
            cp16(sbase + (uint32_t)((VOFF + r*FST + c4) << 2),
                 srcv + (size_t)r*Dx + c4);
        }
    };

    uint32_t aQh[4][4], aQl[4][4];
    {
        const float* q0 = g_q + ((size_t)(b*Nx + qt*64 + warp*16 + g))*Dx + h*64;
        const float* q8 = q0 + 8*Dx;
        #pragma unroll
        for (int ks = 0; ks < 4; ks++) {
            int d0 = 16*ks;
            float e[8] = { q0[d0+2*qd]*SC,   q0[d0+2*qd+1]*SC,
                           q8[d0+2*qd]*SC,   q8[d0+2*qd+1]*SC,
                           q0[d0+8+2*qd]*SC, q0[d0+9+2*qd]*SC,
                           q8[d0+8+2*qd]*SC, q8[d0+9+2*qd]*SC };
            #pragma unroll
            for (int r = 0; r < 4; r++) {
                float h0 = bf16hi_f(e[2*r]), h1 = bf16hi_f(e[2*r+1]);
                aQh[ks][r] = pack_bf16x2(h0, h1);
                aQl[ks][r] = pack_bf16x2(e[2*r]-h0, e[2*r+1]-h1);
            }
        }
    }

    load_K(0, 0);
    cp_commit();

    float Oc[4][2][4] = {};
    float l0 = 0.f, l1 = 0.f;

    for (int kt = 0; kt <= qt; kt++) {
        const int buf = kt & 1;
        cp_wait<0>();
        __syncthreads();
        load_V(kt); cp_commit();
        const bool more = kt < qt;
        if (more) { load_K(kt+1, buf ^ 1); cp_commit(); }

        const uint32_t* Kh2 = fsm + buf*KSET;
        const uint32_t* Kl2 = Kh2 + KMAT;

        float Sc[8][4];
        #pragma unroll
        for (int nf = 0; nf < 8; nf++) {
            Sc[nf][0] = Sc[nf][1] = Sc[nf][2] = Sc[nf][3] = 0.f;
            #pragma unroll
            for (int ks = 0; ks < 4; ks++) {
                int n = nf*8 + g, kbp = ks*8;
                uint32_t bhv[2] = { Kh2[n*KROW + kbp + qd], Kh2[n*KROW + kbp + qd + 4] };
                uint32_t blv[2] = { Kl2[n*KROW + kbp + qd], Kl2[n*KROW + kbp + qd + 4] };
                mma_bf16(Sc[nf], aQh[ks], bhv);
                mma_bf16(Sc[nf], aQh[ks], blv);
                mma_bf16(Sc[nf], aQl[ks], bhv);
            }
        }
        if (kt == qt) {
            int r0 = warp*16 + g, r1 = r0 + 8;
            #pragma unroll
            for (int nf = 0; nf < 8; nf++) {
                int c0 = nf*8 + 2*qd, c1 = c0 + 1;
                if (c0 > r0) Sc[nf][0] = -1e30f;
                if (c1 > r0) Sc[nf][1] = -1e30f;
                if (c0 > r1) Sc[nf][2] = -1e30f;
                if (c1 > r1) Sc[nf][3] = -1e30f;
            }
        }
        #pragma unroll
        for (int nf = 0; nf < 8; nf++) {
            float p0 = __expf(Sc[nf][0]), p1 = __expf(Sc[nf][1]);
            float p2 = __expf(Sc[nf][2]), p3 = __expf(Sc[nf][3]);
            l0 += p0 + p1; l1 += p2 + p3;
            int c0 = nf*8 + 2*qd;
            *(float2*)&Pw[g*FST + c0] =
                make_float2(__uint_as_float(f2tf32(p0)), __uint_as_float(f2tf32(p1)));
            *(float2*)&Pw[(g+8)*FST + c0] =
                make_float2(__uint_as_float(f2tf32(p2)), __uint_as_float(f2tf32(p3)));
        }
        __syncwarp();

        if (more) { cp_wait<1>(); } else { cp_wait<0>(); }
        __syncthreads();

        #pragma unroll
        for (int ks = 0; ks < 8; ks++) {
            int k = ks*8 + qd;
            uint32_t bp0[2] = { __float_as_uint(Pw[g*FST + k]),
                                __float_as_uint(Pw[g*FST + k + 4]) };
            uint32_t bp1[2] = { __float_as_uint(Pw[(8+g)*FST + k]),
                                __float_as_uint(Pw[(8+g)*FST + k + 4]) };
            #pragma unroll
            for (int mf = 0; mf < 4; mf++) {
                uint32_t av[4] = {
                    __float_as_uint(Vs[k*FST + mf*16 + g]),
                    __float_as_uint(Vs[k*FST + mf*16 + g + 8]),
                    __float_as_uint(Vs[(k+4)*FST + mf*16 + g]),
                    __float_as_uint(Vs[(k+4)*FST + mf*16 + g + 8]) };
                mma_tf32(Oc[mf][0], av, bp0);
                mma_tf32(Oc[mf][1], av, bp1);
            }
        }
        __syncwarp();
    }

    l0 += __shfl_xor_sync(0xffffffffu, l0, 1);
    l0 += __shfl_xor_sync(0xffffffffu, l0, 2);
    l1 += __shfl_xor_sync(0xffffffffu, l1, 1);
    l1 += __shfl_xor_sync(0xffffffffu, l1, 2);
    float il0 = 1.f/l0, il1 = 1.f/l1;
    float i00 = __shfl_sync(0xffffffffu, il0, 8*qd);
    float i01 = __shfl_sync(0xffffffffu, il0, 8*qd + 4);
    float i10 = __shfl_sync(0xffffffffu, il1, 8*qd);
    float i11 = __shfl_sync(0xffffffffu, il1, 8*qd + 4);
    int rowbase = b*Nx + qt*64 + warp*16;
    #pragma unroll
    for (int mf = 0; mf < 4; mf++) {
        int d0 = h*64 + mf*16 + g;
        #pragma unroll
        for (int nf = 0; nf < 2; nf++) {
            int r0 = rowbase + nf*8 + 2*qd;
            float ia = nf ? i10 : i00;
            float ib = nf ? i11 : i01;
            g_A[(size_t)r0*Dx + d0]         = Oc[mf][nf][0]*ia;
            g_A[(size_t)(r0+1)*Dx + d0]     = Oc[mf][nf][1]*ib;
            g_A[(size_t)r0*Dx + d0 + 8]     = Oc[mf][nf][2]*ia;
            g_A[(size_t)(r0+1)*Dx + d0 + 8] = Oc[mf][nf][3]*ib;
        }
    }
}

// ---------------------------------------------------------------------------
// Kernel 3: A_mem via bf16 3-pass mma.
// ---------------------------------------------------------------------------
#define AST 36
#define AMEM_SMEM ((2*128*AST + 2*64*AST + 128 + 64)*4)

__global__ __launch_bounds__(128) void amem_mma(const float* __restrict__ mem,
                                                const float* __restrict__ z) {
    extern __shared__ uint32_t as_[];
    uint32_t* Ah2 = as_;
    uint32_t* Al2 = as_ + 128*AST;
    uint32_t* Bh2 = as_ + 2*128*AST;
    uint32_t* Bl2 = Bh2 + 64*AST;
    float* dsh = (float*)(Bl2 + 64*AST);
    float* zsh = dsh + 128;
    const int bh = blockIdx.y;
    const int b = bh >> 3, h = bh & 7;
    const int tid = threadIdx.x, warp = tid >> 5, lane = tid & 31;
    const int g = lane >> 2, qd = lane & 3;
    const int rowbase = b*Nx + blockIdx.x*128;

    if (tid < 64) zsh[tid] = z[bh*64 + tid];
    const float* msrc = mem + bh*4096;
    #pragma unroll
    for (int ii = 0; ii < 16; ii++) {
        int e = tid + 128*ii;
        int o = e >> 5, p = e & 31;
        float m0 = msrc[(2*p)*64 + o], m1 = msrc[(2*p+1)*64 + o];
        float h0 = bf16hi_f(m0), h1 = bf16hi_f(m1);
        Bh2[o*AST + p] = pack_bf16x2(h0, h1);
        Bl2[o*AST + p] = pack_bf16x2(m0 - h0, m1 - h1);
    }
    #pragma unroll
    for (int ii = 0; ii < 16; ii++) {
        int f = tid + 128*ii;
        int r = f >> 4, c = (f & 15) << 2;
        float4 qv = *(const float4*)&g_q[(size_t)(rowbase + r)*Dx + h*64 + c];
        float e0 = qv.x > 0.f ? qv.x + 1.f : __expf(qv.x);
        float e1 = qv.y > 0.f ? qv.y + 1.f : __expf(qv.y);
        float e2 = qv.z > 0.f ? qv.z + 1.f : __expf(qv.z);
        float e3 = qv.w > 0.f ? qv.w + 1.f : __expf(qv.w);
        float h0 = bf16hi_f(e0), h1 = bf16hi_f(e1);
        float h2 = bf16hi_f(e2), h3 = bf16hi_f(e3);
        int wc = c >> 1;
        Ah2[r*AST + wc]     = pack_bf16x2(h0, h1);
        Ah2[r*AST + wc + 1] = pack_bf16x2(h2, h3);
        Al2[r*AST + wc]     = pack_bf16x2(e0-h0, e1-h1);
        Al2[r*AST + wc + 1] = pack_bf16x2(e2-h2, e3-h3);
    }
    __syncthreads();
    {
        float d = 0.f;
        #pragma unroll
        for (int p = 0; p < 32; p++) {
            float2 hh = unpack_bf16x2(Ah2[tid*AST + p]);
            float2 ll = unpack_bf16x2(Al2[tid*AST + p]);
            d += zsh[2*p]*(hh.x + ll.x) + zsh[2*p+1]*(hh.y + ll.y);
        }
        dsh[tid] = d;
    }
    __syncthreads();

    float acc[2][8][4] = {};
    #pragma unroll
    for (int ks = 0; ks < 4; ks++) {
        const int kb = ks*8;
        uint32_t ah[2][4], al[2][4];
        #pragma unroll
        for (int mf = 0; mf < 2; mf++) {
            int r0 = warp*32 + mf*16 + g;
            ah[mf][0] = Ah2[r0*AST + kb + qd];
            ah[mf][1] = Ah2[(r0+8)*AST + kb + qd];
            ah[mf][2] = Ah2[r0*AST + kb + qd + 4];
            ah[mf][3] = Ah2[(r0+8)*AST + kb + qd + 4];
            al[mf][0] = Al2[r0*AST + kb + qd];
            al[mf][1] = Al2[(r0+8)*AST + kb + qd];
            al[mf][2] = Al2[r0*AST + kb + qd + 4];
            al[mf][3] = Al2[(r0+8)*AST + kb + qd + 4];
        }
        #pragma unroll
        for (int nf = 0; nf < 8; nf++) {
            int nr = nf*8 + g;
            uint32_t bhf[2] = { Bh2[nr*AST + kb + qd], Bh2[nr*AST + kb + qd + 4] };
            uint32_t blf[2] = { Bl2[nr*AST + kb + qd], Bl2[nr*AST + kb + qd + 4] };
            #pragma unroll
            for (int mf = 0; mf < 2; mf++) {
                mma_bf16(acc[mf][nf], ah[mf], bhf);
                mma_bf16(acc[mf][nf], ah[mf], blf);
                mma_bf16(acc[mf][nf], al[mf], bhf);
            }
        }
    }
    #pragma unroll
    for (int mf = 0; mf < 2; mf++) {
        int r0 = warp*32 + mf*16 + g;
        float iv0 = 1.f/(dsh[r0]   + 1e-8f);
        float iv1 = 1.f/(dsh[r0+8] + 1e-8f);
        #pragma unroll
        for (int nf = 0; nf < 8; nf++) {
            int c0 = nf*8 + 2*qd;
            *(float2*)&g_Amem[(size_t)(rowbase + r0)*Dx + h*64 + c0] =
                make_float2(acc[mf][nf][0]*iv0, acc[mf][nf][1]*iv0);
            *(float2*)&g_Amem[(size_t)(rowbase + r0 + 8)*Dx + h*64 + c0] =
                make_float2(acc[mf][nf][2]*iv1, acc[mf][nf][3]*iv1);
        }
    }
}

// ---------------------------------------------------------------------------
// Kernel 4: output projection via bf16 3-pass mma, gate mix fused in A-load.
// Block: 128 rows, 256 threads (8 warps, 16 rows each). K chunked in 64s.
// ---------------------------------------------------------------------------
#define PST 36
#define PROJ_SMEM ((2*128*PST + 2*64*PST)*4)   // 55296 B

__global__ __launch_bounds__(256) void gemm_proj_mma(const float* __restrict__ beta,
                                                     float* __restrict__ dout) {
    extern __shared__ uint32_t ps_[];
    uint32_t* Ah2 = ps_;
    uint32_t* Al2 = ps_ + 128*PST;
    uint32_t* Bh2 = ps_ + 2*128*PST;
    uint32_t* Bl2 = Bh2 + 64*PST;
    const int tid = threadIdx.x, warp = tid >> 5, lane = tid & 31;
    const int g = lane >> 2, qd = lane & 3;
    const int rowbase = blockIdx.x*128;
    const float gg = 1.f/(1.f + __expf(-beta[0]));
    const float gi = 1.f - gg;

    float acc[8][4] = {};
    for (int kc = 0; kc < 8; kc++) {
        if (kc) __syncthreads();
        // A chunk: 128 rows x 64 floats, gate-mixed, hi/lo split
        #pragma unroll
        for (int ii = 0; ii < 8; ii++) {
            int f = tid + 256*ii;              // 0..2047 float4 slots
            int r = f >> 4, c = (f & 15) << 2;
            size_t off = (size_t)(rowbase + r)*Dx + kc*64 + c;
            float4 ad = *(const float4*)&g_A[off];
            float4 am = *(const float4*)&g_Amem[off];
            float v0 = gg*am.x + gi*ad.x;
            float v1 = gg*am.y + gi*ad.y;
            float v2 = gg*am.z + gi*ad.z;
            float v3 = gg*am.w + gi*ad.w;
            float h0 = bf16hi_f(v0), h1 = bf16hi_f(v1);
            float h2 = bf16hi_f(v2), h3 = bf16hi_f(v3);
            int wc = c >> 1;
            Ah2[r*PST + wc]     = pack_bf16x2(h0, h1);
            Ah2[r*PST + wc + 1] = pack_bf16x2(h2, h3);
            Al2[r*PST + wc]     = pack_bf16x2(v0-h0, v1-h1);
            Al2[r*PST + wc + 1] = pack_bf16x2(v2-h2, v3-h3);
        }
        // B chunk: Wp^T rows o=64, kpairs kc*32..+32
        #pragma unroll
        for (int ii = 0; ii < 8; ii++) {
            int e = tid + 256*ii;              // 0..2047
            int o = e >> 5, p = e & 31;
            Bh2[o*PST + p] = g_Wph2[o*(Dx/2) + kc*32 + p];
            Bl2[o*PST + p] = g_Wpl2[o*(Dx/2) + kc*32 + p];
        }
        __syncthreads();

        #pragma unroll
        for (int ks = 0; ks < 4; ks++) {
            const int kb = ks*8;
            uint32_t ah[4], al[4];
            int r0 = warp*16 + g;
            ah[0] = Ah2[r0*PST + kb + qd];
            ah[1] = Ah2[(r0+8)*PST + kb + qd];
            ah[2] = Ah2[r0*PST + kb + qd + 4];
            ah[3] = Ah2[(r0+8)*PST + kb + qd + 4];
            al[0] = Al2[r0*PST + kb + qd];
            al[1] = Al2[(r0+8)*PST + kb + qd];
            al[2] = Al2[r0*PST + kb + qd + 4];
            al[3] = Al2[(r0+8)*PST + kb + qd + 4];
            #pragma unroll
            for (int nf = 0; nf < 8; nf++) {
                int nr = nf*8 + g;
                uint32_t bhf[2] = { Bh2[nr*PST + kb + qd], Bh2[nr*PST + kb + qd + 4] };
                uint32_t blf[2] = { Bl2[nr*PST + kb + qd], Bl2[nr*PST + kb + qd + 4] };
                mma_bf16(acc[nf], ah, bhf);
                mma_bf16(acc[nf], ah, blf);
                mma_bf16(acc[nf], al, bhf);
            }
        }
    }
    int r0 = rowbase + warp*16 + g;
    #pragma unroll
    for (int nf = 0; nf < 8; nf++) {
        int c0 = nf*8 + 2*qd;
        *(float2*)&dout[(size_t)r0*Ox + c0]     = make_float2(acc[nf][0], acc[nf][1]);
        *(float2*)&dout[(size_t)(r0+8)*Ox + c0] = make_float2(acc[nf][2], acc[nf][3]);
    }
}

// ---------------------------------------------------------------------------
// Kernel 5: delta-rule update partials (deterministic)
// ---------------------------------------------------------------------------
__global__ __launch_bounds__(256) void update_kernel() {
    __shared__ float ksh[8][64];
    __shared__ float dvsh[8][64];
    int bh = blockIdx.y; int b = bh >> 3, h = bh & 7;
    int chunk = blockIdx.x;
    int tid = threadIdx.x;
    int zb = (tid >> 4) << 2;
    int ob = (tid & 15) << 2;
    float acc[4][4] = {};
    float nz = 0.f;
    int n0base = b*Nx + chunk*256;
    for (int n0 = 0; n0 < 256; n0 += 8) {
        #pragma unroll
        for (int ii = 0; ii < 4; ii++) {
            int f = tid + 256*ii;
            int r = f >> 7;
            int rem = f & 127;
            int bn = n0base + n0 + r;
            if (rem < 64) {
                float kv = g_k[(size_t)bn*Dx + h*64 + rem];
                ksh[r][rem] = kv > 0.f ? kv + 1.f : __expf(kv);
            } else {
                int o = rem - 64;
                dvsh[r][o] = g_v[(size_t)bn*Dx + h*64 + o]
                           - g_Amem[(size_t)bn*Dx + h*64 + o];
            }
        }
        __syncthreads();
        #pragma unroll
        for (int r = 0; r < 8; r++) {
            float kzv[4], dvv[4];
            #pragma unroll
            for (int i = 0; i < 4; i++) { kzv[i] = ksh[r][zb+i]; dvv[i] = dvsh[r][ob+i]; }
            #pragma unroll
            for (int i = 0; i < 4; i++)
                #pragma unroll
                for (int j = 0; j < 4; j++)
                    acc[i][j] += kzv[i]*dvv[j];
        }
        if (tid < 64) {
            #pragma unroll
            for (int r = 0; r < 8; r++) nz += ksh[r][tid];
        }
        __syncthreads();
    }
    float* dstm = &g_part[((size_t)bh*8 + chunk)*4096];
    #pragma unroll
    for (int i = 0; i < 4; i++)
        #pragma unroll
        for (int j = 0; j < 4; j++)
            dstm[(zb+i)*64 + ob+j] = acc[i][j];
    if (tid < 64) g_zpart[((size_t)bh*8 + chunk)*64 + tid] = nz;
}

// ---------------------------------------------------------------------------
// Kernel 6: reduce partials -> next_mem, next_z
// ---------------------------------------------------------------------------
__global__ void reduce_kernel(const float* __restrict__ mem,
                              const float* __restrict__ z,
                              float* __restrict__ dout) {
    int idx = blockIdx.x*blockDim.x + threadIdx.x;
    if (idx < Bx*Hx*Ox*Ox) {
        int bh = idx >> 12, e = idx & 4095;
        float s = mem[idx];
        #pragma unroll
        for (int c = 0; c < 8; c++) s += g_part[((size_t)bh*8 + c)*4096 + e];
        dout[OUT_MEM_OFF + idx] = s;
    } else if (idx < Bx*Hx*Ox*Ox + Bx*Hx*Ox) {
        int t = idx - Bx*Hx*Ox*Ox;
        int bh = t >> 6, e = t & 63;
        float s = z[t];
        #pragma unroll
        for (int c = 0; c < 8; c++) s += g_zpart[((size_t)bh*8 + c)*64 + e];
        dout[OUT_Z_OFF + t] = s;
    }
}

// ---------------------------------------------------------------------------
extern "C" void kernel_launch(void* const* d_in, const int* in_sizes, int n_in,
                              void* d_out, int out_size) {
    const float* inp  = (const float*)d_in[0];
    const float* mem  = (const float*)d_in[1];
    const float* z    = (const float*)d_in[2];
    const float* Wqkv = (const float*)d_in[3];
    const float* Wout = (const float*)d_in[4];
    const float* beta = (const float*)d_in[5];
    float* out = (float*)d_out;

    cudaFuncSetAttribute(gemm_qkv_mma, cudaFuncAttributeMaxDynamicSharedMemorySize,
                         QKV_SMEM_BYTES);
    cudaFuncSetAttribute(flash_mma, cudaFuncAttributeMaxDynamicSharedMemorySize,
                         FLASH_SMEM);
    cudaFuncSetAttribute(amem_mma, cudaFuncAttributeMaxDynamicSharedMemorySize,
                         AMEM_SMEM);
    cudaFuncSetAttribute(gemm_proj_mma, cudaFuncAttributeMaxDynamicSharedMemorySize,
                         PROJ_SMEM);

    TSArr ts;
    for (int i = 0; i < Dx; i++)
        ts.v[i] = (float)exp(log(1e-3) * (double)(2*(i/2)) / (double)Dx);

    // Main: prep -> xsplit -> gemm -> flash -> (join) -> proj
    // Side (forked after gemm): amem -> update -> reduce, concurrent w/ flash.
    prep_kernel<<<PE_BLOCKS + WT_BLOCKS + PW_BLOCKS, 256>>>(ts, Wqkv, Wout);   // 0
    xsplit_kernel<<<(ROWS*Dx/8 + 255)/256, 256>>>(inp);                        // 1
    gemm_qkv_mma<<<dim3(QKVCOLS/128, ROWS/128), 512, QKV_SMEM_BYTES>>>(0);     // 2

    cudaEventRecord(g_ss.e_fork, 0);
    cudaStreamWaitEvent(g_ss.s, g_ss.e_fork, 0);

    flash_mma<<<dim3(Nx/64, Bx*Hx), 128, FLASH_SMEM>>>();                      // 3 (profiled)
    amem_mma<<<dim3(Nx/128, Bx*Hx), 128, AMEM_SMEM, g_ss.s>>>(mem, z);         // 4
    update_kernel<<<dim3(8, Bx*Hx), 256, 0, g_ss.s>>>();                       // 5
    reduce_kernel<<<(Bx*Hx*Ox*Ox + Bx*Hx*Ox + 255)/256, 256, 0, g_ss.s>>>(mem, z, out); // 6

    cudaEventRecord(g_ss.e_join, g_ss.s);
    cudaStreamWaitEvent(0, g_ss.e_join, 0);

    gemm_proj_mma<<<ROWS/128, 256, PROJ_SMEM>>>(beta, out);                    // 7
}

// round 17
// speedup vs baseline: 1.0185x; 1.0185x over previous
#include <cuda_runtime.h>
#include <cuda_bf16.h>
#include <math.h>
#include <cstdint>

// Problem dims
#define Bx 4
#define Nx 2048
#define Dx 512
#define Hx 8
#define Ox 64
#define ROWS (Bx*Nx)      // 8192
#define QKVCOLS (Hx*Ox*3) // 1536

// d_out packing: out (B,N,64) | next_mem (B,H,64,64) | next_z (B,H,64)
#define OUT_MEM_OFF (ROWS*Ox)
#define OUT_Z_OFF   (OUT_MEM_OFF + Bx*Hx*Ox*Ox)

// Scratch
__device__ uint32_t g_xh2[ROWS*Dx/2];
__device__ uint32_t g_xl2[ROWS*Dx/2];
__device__ uint32_t g_Wth2[QKVCOLS*Dx/2];
__device__ uint32_t g_Wtl2[QKVCOLS*Dx/2];
__device__ float g_q[ROWS*Dx];
__device__ float g_k[ROWS*Dx];
__device__ float g_v[ROWS*Dx];
__device__ uint32_t g_kh2[ROWS*Dx/2];
__device__ uint32_t g_kl2[ROWS*Dx/2];
__device__ float g_vt[ROWS*Dx];
__device__ float g_Amem[ROWS*Dx];
__device__ float g_A[ROWS*Dx];
__device__ float g_Wp[Dx*Ox];
__device__ float g_part[32*8*Ox*Ox];
__device__ float g_zpart[32*8*Ox];

struct TSArr { float v[Dx]; };

// Side stream + events, created once at static init (no allocs in kernel_launch).
struct SideStream {
    cudaStream_t s;
    cudaEvent_t e_start, e_fork, e_join, e_wjoin;
    SideStream() {
        cudaStreamCreateWithFlags(&s, cudaStreamNonBlocking);
        cudaEventCreateWithFlags(&e_start, cudaEventDisableTiming);
        cudaEventCreateWithFlags(&e_fork, cudaEventDisableTiming);
        cudaEventCreateWithFlags(&e_join, cudaEventDisableTiming);
        cudaEventCreateWithFlags(&e_wjoin, cudaEventDisableTiming);
    }
};
static SideStream g_ss;

// ---------------------------------------------------------------------------
// helpers (plain sm_80+ PTX)
// ---------------------------------------------------------------------------
__device__ __forceinline__ uint32_t f2tf32(float x) {
    uint32_t r;
    asm("cvt.rna.tf32.f32 %0, %1;" : "=r"(r) : "f"(x));
    return r;
}
__device__ __forceinline__ void mma_tf32(float* c, const uint32_t* a, const uint32_t* b) {
    asm volatile("mma.sync.aligned.m16n8k8.row.col.f32.tf32.tf32.f32 "
        "{%0,%1,%2,%3}, {%4,%5,%6,%7}, {%8,%9}, {%0,%1,%2,%3};"
        : "+f"(c[0]), "+f"(c[1]), "+f"(c[2]), "+f"(c[3])
        : "r"(a[0]), "r"(a[1]), "r"(a[2]), "r"(a[3]), "r"(b[0]), "r"(b[1]));
}
__device__ __forceinline__ void mma_bf16(float* c, const uint32_t* a, const uint32_t* b) {
    asm volatile("mma.sync.aligned.m16n8k16.row.col.f32.bf16.bf16.f32 "
        "{%0,%1,%2,%3}, {%4,%5,%6,%7}, {%8,%9}, {%0,%1,%2,%3};"
        : "+f"(c[0]), "+f"(c[1]), "+f"(c[2]), "+f"(c[3])
        : "r"(a[0]), "r"(a[1]), "r"(a[2]), "r"(a[3]), "r"(b[0]), "r"(b[1]));
}
__device__ __forceinline__ uint32_t pack_bf16x2(float e0, float e1) {
    uint32_t d;
    asm("cvt.rn.bf16x2.f32 %0, %1, %2;" : "=r"(d) : "f"(e1), "f"(e0));
    return d;
}
__device__ __forceinline__ float bf16hi_f(float x) {
    return __bfloat162float(__float2bfloat16(x));
}
__device__ __forceinline__ float2 unpack_bf16x2(uint32_t w) {
    __nv_bfloat162 b = *(__nv_bfloat162*)&w;
    return make_float2(__bfloat162float(b.x), __bfloat162float(b.y));
}
__device__ __forceinline__ uint32_t smem_u32(const void* p) {
    uint32_t a;
    asm("{ .reg .u64 t; cvta.to.shared.u64 t, %1; cvt.u32.u64 %0, t; }" : "=r"(a) : "l"(p));
    return a;
}
__device__ __forceinline__ void cp16(uint32_t dst, const void* src) {
    asm volatile("cp.async.ca.shared.global [%0], [%1], 16;" :: "r"(dst), "l"(src));
}
__device__ __forceinline__ void cp_commit() { asm volatile("cp.async.commit_group;" ::: "memory"); }
template<int N> __device__ __forceinline__ void cp_wait() {
    asm volatile("cp.async.wait_group %0;" :: "n"(N) : "memory");
}

// ---------------------------------------------------------------------------
// Kernel W: weight prep (side stream) — W transpose+split | Wp permute
// ---------------------------------------------------------------------------
#define WT_BLOCKS 768
#define PW_BLOCKS 128
__global__ __launch_bounds__(256) void wprep_kernel(const float* __restrict__ wk,
                                                    const float* __restrict__ wo) {
    __shared__ float t[32][33];
    int bid = blockIdx.x;
    if (bid < WT_BLOCKS) {
        const int colBase = (bid % 48)*32;
        const int kBase   = (bid / 48)*32;
        const int tx = threadIdx.x & 31, ty = threadIdx.x >> 5;
        #pragma unroll
        for (int j = ty; j < 32; j += 8)
            t[j][tx] = wk[(size_t)(kBase + j)*QKVCOLS + colBase + tx];
        __syncthreads();
        #pragma unroll
        for (int it = 0; it < 2; it++) {
            int e = threadIdx.x + 256*it;
            int j = e >> 4;
            int p = e & 15;
            int col  = colBase + j;
            int orow = (col % 3)*512 + col/3;
            float w0 = t[2*p][j],  w1 = t[2*p+1][j];
            float h0 = bf16hi_f(w0), h1 = bf16hi_f(w1);
            size_t o = (size_t)orow*(Dx/2) + (kBase>>1) + p;
            g_Wth2[o] = pack_bf16x2(h0, h1);
            g_Wtl2[o] = pack_bf16x2(w0 - h0, w1 - h1);
        }
    } else {
        int idx = (bid - WT_BLOCKS)*256 + threadIdx.x;
        int o  = idx & 63;
        int hi = idx >> 6;
        int h  = hi >> 6;
        int i  = hi & 63;
        g_Wp[idx] = wo[(i*Hx + h)*Ox + o];
    }
}

// ---------------------------------------------------------------------------
// Kernel X: fused PE + x-split.  One thread = one (n, i-pair); PE computed
// once (pair shares one timescale: sin for even i, cos for odd i), applied to
// all 4 batch rows, bf16 hi/lo split, kpair-packed. No g_pe round-trip.
// ---------------------------------------------------------------------------
__global__ __launch_bounds__(256) void xfuse_kernel(TSArr ts, const float* __restrict__ in) {
    int e = blockIdx.x*256 + threadIdx.x;     // 0 .. Nx*Dx/2-1
    int p = e & 255;                          // i-pair 0..255
    int n = e >> 8;                           // 0..2047
    float ang = (float)n * ts.v[2*p];
    const float C1 = 6.28125f;
    const float C2 = (float)(6.283185307179586 - 6.28125);
    const float C3 = (float)(6.283185307179586 - 6.28125
                             - (double)(float)(6.283185307179586 - 6.28125));
    float k = rintf(ang * 0.15915494309189535f);
    float r = fmaf(-k, C1, ang);
    r = fmaf(-k, C2, r);
    r = fmaf(-k, C3, r);
    float pe0 = sinf(r);        // even i
    float pe1 = cosf(r);        // odd i
    #pragma unroll
    for (int b = 0; b < Bx; b++) {
        size_t row = (size_t)b*Nx + n;
        float2 xv = *(const float2*)&in[row*Dx + 2*p];
        float v0 = xv.x + pe0, v1 = xv.y + pe1;
        float h0 = bf16hi_f(v0), h1 = bf16hi_f(v1);
        g_xh2[row*(Dx/2) + p] = pack_bf16x2(h0, h1);
        g_xl2[row*(Dx/2) + p] = pack_bf16x2(v0 - h0, v1 - h1);
    }
}

// ---------------------------------------------------------------------------
// Kernel 1: bf16 m16n8k16 hi/lo 3-pass QKV GEMM, cp.async double-buffered.
// Epilogue also emits k hi/lo packed + v tf32 for flash.
// ---------------------------------------------------------------------------
#define TWB 16
#define TILE_WORDS_B (128*TWB)
#define QKV_SMEM_BYTES (8*TILE_WORDS_B*4)    // 65536

__device__ __forceinline__ int swzb(int r, int c) { return r*TWB + (c ^ (((r>>1)&3)<<2)); }

__global__ __launch_bounds__(512) void gemm_qkv_mma(int dummy) {
    extern __shared__ uint32_t sm[];
    const uint32_t sbase = smem_u32(sm);
    const int tid  = threadIdx.x;
    const int warp = tid >> 5;
    const int lane = tid & 31;
    const int wm = warp >> 2;
    const int wn = warp & 3;
    const int bm = blockIdx.y * 128;
    const int bn = blockIdx.x * 128;
    const int g = lane >> 2;
    const int q = lane & 3;

    float acc[2][4][4] = {};

    auto load_chunk = [&](int s, int buf) {
        #pragma unroll
        for (int t = 0; t < 4; t++) {
            const uint32_t* src = (t==0) ? g_xh2 : (t==1) ? g_xl2 : (t==2) ? g_Wth2 : g_Wtl2;
            const int rowbase = (t < 2) ? bm : bn;
            int r = tid >> 2, cg = (tid & 3) << 2;
            uint32_t dst = sbase + (uint32_t)(((buf*4 + t)*TILE_WORDS_B + swzb(r, cg)) << 2);
            cp16(dst, src + (size_t)(rowbase + r)*(Dx/2) + s*TWB + cg);
        }
    };

    load_chunk(0, 0);
    cp_commit();

    for (int s = 0; s < 16; s++) {
        const int buf = s & 1;
        if (s + 1 < 16) {
            load_chunk(s+1, buf ^ 1);
            cp_commit();
            cp_wait<1>();
        } else {
            cp_wait<0>();
        }
        __syncthreads();

        const uint32_t* Xh = sm + (buf*4 + 0)*TILE_WORDS_B;
        const uint32_t* Xl = sm + (buf*4 + 1)*TILE_WORDS_B;
        const uint32_t* Wh = sm + (buf*4 + 2)*TILE_WORDS_B;
        const uint32_t* Wl = sm + (buf*4 + 3)*TILE_WORDS_B;

        #pragma unroll
        for (int ks = 0; ks < 2; ks++) {
            const int kb = ks*8;
            uint32_t ah[2][4], al[2][4], bh[4][2], bl[4][2];
            #pragma unroll
            for (int mf = 0; mf < 2; mf++) {
                int r0 = wm*32 + mf*16 + g;
                ah[mf][0] = Xh[swzb(r0,   kb+q)];
                ah[mf][1] = Xh[swzb(r0+8, kb+q)];
                ah[mf][2] = Xh[swzb(r0,   kb+q+4)];
                ah[mf][3] = Xh[swzb(r0+8, kb+q+4)];
                al[mf][0] = Xl[swzb(r0,   kb+q)];
                al[mf][1] = Xl[swzb(r0+8, kb+q)];
                al[mf][2] = Xl[swzb(r0,   kb+q+4)];
                al[mf][3] = Xl[swzb(r0+8, kb+q+4)];
            }
            #pragma unroll
            for (int nf = 0; nf < 4; nf++) {
                int nc = wn*32 + nf*8 + g;
                bh[nf][0] = Wh[swzb(nc, kb+q)];
                bh[nf][1] = Wh[swzb(nc, kb+q+4)];
                bl[nf][0] = Wl[swzb(nc, kb+q)];
                bl[nf][1] = Wl[swzb(nc, kb+q+4)];
            }
            #pragma unroll
            for (int mf = 0; mf < 2; mf++)
                #pragma unroll
                for (int nf = 0; nf < 4; nf++) {
                    mma_bf16(acc[mf][nf], ah[mf], bh[nf]);
                    mma_bf16(acc[mf][nf], ah[mf], bl[nf]);
                    mma_bf16(acc[mf][nf], al[mf], bh[nf]);
                }
        }
        __syncthreads();
    }

    const int sec = bn >> 9;
    const int nb  = bn & 511;
    #pragma unroll
    for (int mf = 0; mf < 2; mf++) {
        int m = bm + wm*32 + mf*16 + g;
        #pragma unroll
        for (int nf = 0; nf < 4; nf++) {
            int col = nb + wn*32 + nf*8 + q*2;
            float a0 = acc[mf][nf][0], a1 = acc[mf][nf][1];
            float a2 = acc[mf][nf][2], a3 = acc[mf][nf][3];
            if (sec == 0) {
                *(float2*)&g_k[(size_t)m*Dx + col]     = make_float2(a0, a1);
                *(float2*)&g_k[(size_t)(m+8)*Dx + col] = make_float2(a2, a3);
                float h0 = bf16hi_f(a0), h1 = bf16hi_f(a1);
                float h2 = bf16hi_f(a2), h3 = bf16hi_f(a3);
                int wc = col >> 1;
                g_kh2[(size_t)m*(Dx/2) + wc]     = pack_bf16x2(h0, h1);
                g_kl2[(size_t)m*(Dx/2) + wc]     = pack_bf16x2(a0-h0, a1-h1);
                g_kh2[(size_t)(m+8)*(Dx/2) + wc] = pack_bf16x2(h2, h3);
                g_kl2[(size_t)(m+8)*(Dx/2) + wc] = pack_bf16x2(a2-h2, a3-h3);
            } else if (sec == 1) {
                *(float2*)&g_v[(size_t)m*Dx + col]     = make_float2(a0, a1);
                *(float2*)&g_v[(size_t)(m+8)*Dx + col] = make_float2(a2, a3);
                *(float2*)&g_vt[(size_t)m*Dx + col] =
                    make_float2(__uint_as_float(f2tf32(a0)), __uint_as_float(f2tf32(a1)));
                *(float2*)&g_vt[(size_t)(m+8)*Dx + col] =
                    make_float2(__uint_as_float(f2tf32(a2)), __uint_as_float(f2tf32(a3)));
            } else {
                *(float2*)&g_q[(size_t)m*Dx + col]     = make_float2(a0, a1);
                *(float2*)&g_q[(size_t)(m+8)*Dx + col] = make_float2(a2, a3);
            }
        }
    }
}

// ---------------------------------------------------------------------------
// Kernel 2: causal flash attention (R12/R14 version, unchanged)
// ---------------------------------------------------------------------------
#define FST 68
#define KROW 36
#define KMAT (64*KROW)
#define KSET (2*KMAT)
#define VOFF (2*KSET)
#define POFF (VOFF + 64*FST)
#define FLASH_SMEM ((POFF + 4*16*FST)*4)   // 71680 B

__global__ __launch_bounds__(128, 3) void flash_mma() {
    extern __shared__ uint32_t fsm[];
    const uint32_t sbase = smem_u32(fsm);
    float* Vs = (float*)(fsm + VOFF);
    const int bh = blockIdx.y;
    const int b = bh >> 3, h = bh & 7;
    const int qt = gridDim.x - 1 - blockIdx.x;
    const int tid = threadIdx.x, warp = tid >> 5, lane = tid & 31;
    const int g = lane >> 2, qd = lane & 3;
    float* Pw = (float*)(fsm + POFF) + warp*16*FST;

    const float SC = 0.04419417382415922f;

    auto load_K = [&](int kt, int buf) {
        const uint32_t* srch = g_kh2 + ((size_t)(b*Nx + kt*64))*(Dx/2) + h*32;
        const uint32_t* srcl = g_kl2 + ((size_t)(b*Nx + kt*64))*(Dx/2) + h*32;
        #pragma unroll
        for (int ii = 0; ii < 4; ii++) {
            int f = tid + 128*ii;
            int r = f >> 3, c4 = (f & 7) << 2;
            cp16(sbase + (uint32_t)((buf*KSET + r*KROW + c4) << 2),
                 srch + (size_t)r*(Dx/2) + c4);
            cp16(sbase + (uint32_t)((buf*KSET + KMAT + r*KROW + c4) << 2),
                 srcl + (size_t)r*(Dx/2) + c4);
        }
    };
    auto load_V = [&](int kt) {
        const float* srcv = g_vt + ((size_t)(b*Nx + kt*64))*Dx + h*64;
        #pragma unroll
        for (int ii = 0; ii < 8; ii++) {
            int f = tid + 128*ii;
            int r = f >> 4, c4 = (f & 15) << 2;
            cp16(sbase + (uint32_t)((VOFF + r*FST + c4) << 2),
                 srcv + (size_t)r*Dx + c4);
        }
    };

    uint32_t aQh[4][4], aQl[4][4];
    {
        const float* q0 = g_q + ((size_t)(b*Nx + qt*64 + warp*16 + g))*Dx + h*64;
        const float* q8 = q0 + 8*Dx;
        #pragma unroll
        for (int ks = 0; ks < 4; ks++) {
            int d0 = 16*ks;
            float e[8] = { q0[d0+2*qd]*SC,   q0[d0+2*qd+1]*SC,
                           q8[d0+2*qd]*SC,   q8[d0+2*qd+1]*SC,
                           q0[d0+8+2*qd]*SC, q0[d0+9+2*qd]*SC,
                           q8[d0+8+2*qd]*SC, q8[d0+9+2*qd]*SC };
            #pragma unroll
            for (int r = 0; r < 4; r++) {
                float h0 = bf16hi_f(e[2*r]), h1 = bf16hi_f(e[2*r+1]);
                aQh[ks][r] = pack_bf16x2(h0, h1);
                aQl[ks][r] = pack_bf16x2(e[2*r]-h0, e[2*r+1]-h1);
            }
        }
    }

    load_K(0, 0);
    cp_commit();

    float Oc[4][2][4] = {};
    float l0 = 0.f, l1 = 0.f;

    for (int kt = 0; kt <= qt; kt++) {
        const int buf = kt & 1;
        cp_wait<0>();
        __syncthreads();
        load_V(kt); cp_commit();
        const bool more = kt < qt;
        if (more) { load_K(kt+1, buf ^ 1); cp_commit(); }

        const uint32_t* Kh2 = fsm + buf*KSET;
        const uint32_t* Kl2 = Kh2 + KMAT;

        float Sc[8][4];
        #pragma unroll
        for (int nf = 0; nf < 8; nf++) {
            Sc[nf][0] = Sc[nf][1] = Sc[nf][2] = Sc[nf][3] = 0.f;
            #pragma unroll
            for (int ks = 0; ks < 4; ks++) {
                int n = nf*8 + g, kbp = ks*8;
                uint32_t bhv[2] = { Kh2[n*KROW + kbp + qd], Kh2[n*KROW + kbp + qd + 4] };
                uint32_t blv[2] = { Kl2[n*KROW + kbp + qd], Kl2[n*KROW + kbp + qd + 4] };
                mma_bf16(Sc[nf], aQh[ks], bhv);
                mma_bf16(Sc[nf], aQh[ks], blv);
                mma_bf16(Sc[nf], aQl[ks], bhv);
            }
        }
        if (kt == qt) {
            int r0 = warp*16 + g, r1 = r0 + 8;
            #pragma unroll
            for (int nf = 0; nf < 8; nf++) {
                int c0 = nf*8 + 2*qd, c1 = c0 + 1;
                if (c0 > r0) Sc[nf][0] = -1e30f;
                if (c1 > r0) Sc[nf][1] = -1e30f;
                if (c0 > r1) Sc[nf][2] = -1e30f;
                if (c1 > r1) Sc[nf][3] = -1e30f;
            }
        }
        #pragma unroll
        for (int nf = 0; nf < 8; nf++) {
            float p0 = __expf(Sc[nf][0]), p1 = __expf(Sc[nf][1]);
            float p2 = __expf(Sc[nf][2]), p3 = __expf(Sc[nf][3]);
            l0 += p0 + p1; l1 += p2 + p3;
            int c0 = nf*8 + 2*qd;
            *(float2*)&Pw[g*FST + c0] =
                make_float2(__uint_as_float(f2tf32(p0)), __uint_as_float(f2tf32(p1)));
            *(float2*)&Pw[(g+8)*FST + c0] =
                make_float2(__uint_as_float(f2tf32(p2)), __uint_as_float(f2tf32(p3)));
        }
        __syncwarp();

        if (more) { cp_wait<1>(); } else { cp_wait<0>(); }
        __syncthreads();

        #pragma unroll
        for (int ks = 0; ks < 8; ks++) {
            int k = ks*8 + qd;
            uint32_t bp0[2] = { __float_as_uint(Pw[g*FST + k]),
                                __float_as_uint(Pw[g*FST + k + 4]) };
            uint32_t bp1[2] = { __float_as_uint(Pw[(8+g)*FST + k]),
                                __float_as_uint(Pw[(8+g)*FST + k + 4]) };
            #pragma unroll
            for (int mf = 0; mf < 4; mf++) {
                uint32_t av[4] = {
                    __float_as_uint(Vs[k*FST + mf*16 + g]),
                    __float_as_uint(Vs[k*FST + mf*16 + g + 8]),
                    __float_as_uint(Vs[(k+4)*FST + mf*16 + g]),
                    __float_as_uint(Vs[(k+4)*FST + mf*16 + g + 8]) };
                mma_tf32(Oc[mf][0], av, bp0);
                mma_tf32(Oc[mf][1], av, bp1);
            }
        }
        __syncwarp();
    }

    l0 += __shfl_xor_sync(0xffffffffu, l0, 1);
    l0 += __shfl_xor_sync(0xffffffffu, l0, 2);
    l1 += __shfl_xor_sync(0xffffffffu, l1, 1);
    l1 += __shfl_xor_sync(0xffffffffu, l1, 2);
    float il0 = 1.f/l0, il1 = 1.f/l1;
    float i00 = __shfl_sync(0xffffffffu, il0, 8*qd);
    float i01 = __shfl_sync(0xffffffffu, il0, 8*qd + 4);
    float i10 = __shfl_sync(0xffffffffu, il1, 8*qd);
    float i11 = __shfl_sync(0xffffffffu, il1, 8*qd + 4);
    int rowbase = b*Nx + qt*64 + warp*16;
    #pragma unroll
    for (int mf = 0; mf < 4; mf++) {
        int d0 = h*64 + mf*16 + g;
        #pragma unroll
        for (int nf = 0; nf < 2; nf++) {
            int r0 = rowbase + nf*8 + 2*qd;
            float ia = nf ? i10 : i00;
            float ib = nf ? i11 : i01;
            g_A[(size_t)r0*Dx + d0]         = Oc[mf][nf][0]*ia;
            g_A[(size_t)(r0+1)*Dx + d0]     = Oc[mf][nf][1]*ib;
            g_A[(size_t)r0*Dx + d0 + 8]     = Oc[mf][nf][2]*ia;
            g_A[(size_t)(r0+1)*Dx + d0 + 8] = Oc[mf][nf][3]*ib;
        }
    }
}

// ---------------------------------------------------------------------------
// Kernel 3: A_mem via bf16 3-pass mma.
// ---------------------------------------------------------------------------
#define AST 36
#define AMEM_SMEM ((2*128*AST + 2*64*AST + 128 + 64)*4)

__global__ __launch_bounds__(128) void amem_mma(const float* __restrict__ mem,
                                                const float* __restrict__ z) {
    extern __shared__ uint32_t as_[];
    uint32_t* Ah2 = as_;
    uint32_t* Al2 = as_ + 128*AST;
    uint32_t* Bh2 = as_ + 2*128*AST;
    uint32_t* Bl2 = Bh2 + 64*AST;
    float* dsh = (float*)(Bl2 + 64*AST);
    float* zsh = dsh + 128;
    const int bh = blockIdx.y;
    const int b = bh >> 3, h = bh & 7;
    const int tid = threadIdx.x, warp = tid >> 5, lane = tid & 31;
    const int g = lane >> 2, qd = lane & 3;
    const int rowbase = b*Nx + blockIdx.x*128;

    if (tid < 64) zsh[tid] = z[bh*64 + tid];
    const float* msrc = mem + bh*4096;
    #pragma unroll
    for (int ii = 0; ii < 16; ii++) {
        int e = tid + 128*ii;
        int o = e >> 5, p = e & 31;
        float m0 = msrc[(2*p)*64 + o], m1 = msrc[(2*p+1)*64 + o];
        float h0 = bf16hi_f(m0), h1 = bf16hi_f(m1);
        Bh2[o*AST + p] = pack_bf16x2(h0, h1);
        Bl2[o*AST + p] = pack_bf16x2(m0 - h0, m1 - h1);
    }
    #pragma unroll
    for (int ii = 0; ii < 16; ii++) {
        int f = tid + 128*ii;
        int r = f >> 4, c = (f & 15) << 2;
        float4 qv = *(const float4*)&g_q[(size_t)(rowbase + r)*Dx + h*64 + c];
        float e0 = qv.x > 0.f ? qv.x + 1.f : __expf(qv.x);
        float e1 = qv.y > 0.f ? qv.y + 1.f : __expf(qv.y);
        float e2 = qv.z > 0.f ? qv.z + 1.f : __expf(qv.z);
        float e3 = qv.w > 0.f ? qv.w + 1.f : __expf(qv.w);
        float h0 = bf16hi_f(e0), h1 = bf16hi_f(e1);
        float h2 = bf16hi_f(e2), h3 = bf16hi_f(e3);
        int wc = c >> 1;
        Ah2[r*AST + wc]     = pack_bf16x2(h0, h1);
        Ah2[r*AST + wc + 1] = pack_bf16x2(h2, h3);
        Al2[r*AST + wc]     = pack_bf16x2(e0-h0, e1-h1);
        Al2[r*AST + wc + 1] = pack_bf16x2(e2-h2, e3-h3);
    }
    __syncthreads();
    {
        float d = 0.f;
        #pragma unroll
        for (int p = 0; p < 32; p++) {
            float2 hh = unpack_bf16x2(Ah2[tid*AST + p]);
            float2 ll = unpack_bf16x2(Al2[tid*AST + p]);
            d += zsh[2*p]*(hh.x + ll.x) + zsh[2*p+1]*(hh.y + ll.y);
        }
        dsh[tid] = d;
    }
    __syncthreads();

    float acc[2][8][4] = {};
    #pragma unroll
    for (int ks = 0; ks < 4; ks++) {
        const int kb = ks*8;
        uint32_t ah[2][4], al[2][4];
        #pragma unroll
        for (int mf = 0; mf < 2; mf++) {
            int r0 = warp*32 + mf*16 + g;
            ah[mf][0] = Ah2[r0*AST + kb + qd];
            ah[mf][1] = Ah2[(r0+8)*AST + kb + qd];
            ah[mf][2] = Ah2[r0*AST + kb + qd + 4];
            ah[mf][3] = Ah2[(r0+8)*AST + kb + qd + 4];
            al[mf][0] = Al2[r0*AST + kb + qd];
            al[mf][1] = Al2[(r0+8)*AST + kb + qd];
            al[mf][2] = Al2[r0*AST + kb + qd + 4];
            al[mf][3] = Al2[(r0+8)*AST + kb + qd + 4];
        }
        #pragma unroll
        for (int nf = 0; nf < 8; nf++) {
            int nr = nf*8 + g;
            uint32_t bhf[2] = { Bh2[nr*AST + kb + qd], Bh2[nr*AST + kb + qd + 4] };
            uint32_t blf[2] = { Bl2[nr*AST + kb + qd], Bl2[nr*AST + kb + qd + 4] };
            #pragma unroll
            for (int mf = 0; mf < 2; mf++) {
                mma_bf16(acc[mf][nf], ah[mf], bhf);
                mma_bf16(acc[mf][nf], ah[mf], blf);
                mma_bf16(acc[mf][nf], al[mf], bhf);
            }
        }
    }
    #pragma unroll
    for (int mf = 0; mf < 2; mf++) {
        int r0 = warp*32 + mf*16 + g;
        float iv0 = 1.f/(dsh[r0]   + 1e-8f);
        float iv1 = 1.f/(dsh[r0+8] + 1e-8f);
        #pragma unroll
        for (int nf = 0; nf < 8; nf++) {
            int c0 = nf*8 + 2*qd;
            *(float2*)&g_Amem[(size_t)(rowbase + r0)*Dx + h*64 + c0] =
                make_float2(acc[mf][nf][0]*iv0, acc[mf][nf][1]*iv0);
            *(float2*)&g_Amem[(size_t)(rowbase + r0 + 8)*Dx + h*64 + c0] =
                make_float2(acc[mf][nf][2]*iv1, acc[mf][nf][3]*iv1);
        }
    }
}

// ---------------------------------------------------------------------------
// Kernel 4: output projection with fused gate mix (SIMT, R14 version)
// ---------------------------------------------------------------------------
__global__ __launch_bounds__(256) void gemm_proj(const float* __restrict__ beta,
                                                 float* __restrict__ dout) {
    __shared__ float As[16][64];
    __shared__ float Bs[16][64];
    const int bm = blockIdx.x * 64;
    const int tid = threadIdx.x;
    const int tx = tid & 15, ty = tid >> 4;
    const float gg = 1.f/(1.f + __expf(-beta[0]));
    const float gi = 1.f - gg;
    float acc[4][4] = {};
    for (int k0 = 0; k0 < Dx; k0 += 16) {
        {
            int r = tid >> 2; int c = (tid & 3) << 2;
            float4 ad = *(const float4*)&g_A[(bm + r)*Dx + k0 + c];
            float4 am = *(const float4*)&g_Amem[(bm + r)*Dx + k0 + c];
            As[c+0][r] = gg*am.x + gi*ad.x;
            As[c+1][r] = gg*am.y + gi*ad.y;
            As[c+2][r] = gg*am.z + gi*ad.z;
            As[c+3][r] = gg*am.w + gi*ad.w;
        }
        {
            int r = tid >> 4; int c = (tid & 15) << 2;
            *(float4*)&Bs[r][c] = *(const float4*)&g_Wp[(k0 + r)*Ox + c];
        }
        __syncthreads();
        #pragma unroll
        for (int kk = 0; kk < 16; kk++) {
            float4 a = *(const float4*)&As[kk][ty<<2];
            float4 b = *(const float4*)&Bs[kk][tx<<2];
            float av[4] = {a.x,a.y,a.z,a.w};
            float bv[4] = {b.x,b.y,b.z,b.w};
            #pragma unroll
            for (int i = 0; i < 4; i++)
                #pragma unroll
                for (int j = 0; j < 4; j++)
                    acc[i][j] += av[i]*bv[j];
        }
        __syncthreads();
    }
    #pragma unroll
    for (int i = 0; i < 4; i++)
        #pragma unroll
        for (int j = 0; j < 4; j++)
            dout[(bm + (ty<<2) + i)*Ox + (tx<<2) + j] = acc[i][j];
}

// ---------------------------------------------------------------------------
// Kernel 5: delta-rule update partials (deterministic)
// ---------------------------------------------------------------------------
__global__ __launch_bounds__(256) void update_kernel() {
    __shared__ float ksh[8][64];
    __shared__ float dvsh[8][64];
    int bh = blockIdx.y; int b = bh >> 3, h = bh & 7;
    int chunk = blockIdx.x;
    int tid = threadIdx.x;
    int zb = (tid >> 4) << 2;
    int ob = (tid & 15) << 2;
    float acc[4][4] = {};
    float nz = 0.f;
    int n0base = b*Nx + chunk*256;
    for (int n0 = 0; n0 < 256; n0 += 8) {
        #pragma unroll
        for (int ii = 0; ii < 4; ii++) {
            int f = tid + 256*ii;
            int r = f >> 7;
            int rem = f & 127;
            int bn = n0base + n0 + r;
            if (rem < 64) {
                float kv = g_k[(size_t)bn*Dx + h*64 + rem];
                ksh[r][rem] = kv > 0.f ? kv + 1.f : __expf(kv);
            } else {
                int o = rem - 64;
                dvsh[r][o] = g_v[(size_t)bn*Dx + h*64 + o]
                           - g_Amem[(size_t)bn*Dx + h*64 + o];
            }
        }
        __syncthreads();
        #pragma unroll
        for (int r = 0; r < 8; r++) {
            float kzv[4], dvv[4];
            #pragma unroll
            for (int i = 0; i < 4; i++) { kzv[i] = ksh[r][zb+i]; dvv[i] = dvsh[r][ob+i]; }
            #pragma unroll
            for (int i = 0; i < 4; i++)
                #pragma unroll
                for (int j = 0; j < 4; j++)
                    acc[i][j] += kzv[i]*dvv[j];
        }
        if (tid < 64) {
            #pragma unroll
            for (int r = 0; r < 8; r++) nz += ksh[r][tid];
        }
        __syncthreads();
    }
    float* dstm = &g_part[((size_t)bh*8 + chunk)*4096];
    #pragma unroll
    for (int i = 0; i < 4; i++)
        #pragma unroll
        for (int j = 0; j < 4; j++)
            dstm[(zb+i)*64 + ob+j] = acc[i][j];
    if (tid < 64) g_zpart[((size_t)bh*8 + chunk)*64 + tid] = nz;
}

// ---------------------------------------------------------------------------
// Kernel 6: reduce partials -> next_mem, next_z
// ---------------------------------------------------------------------------
__global__ void reduce_kernel(const float* __restrict__ mem,
                              const float* __restrict__ z,
                              float* __restrict__ dout) {
    int idx = blockIdx.x*blockDim.x + threadIdx.x;
    if (idx < Bx*Hx*Ox*Ox) {
        int bh = idx >> 12, e = idx & 4095;
        float s = mem[idx];
        #pragma unroll
        for (int c = 0; c < 8; c++) s += g_part[((size_t)bh*8 + c)*4096 + e];
        dout[OUT_MEM_OFF + idx] = s;
    } else if (idx < Bx*Hx*Ox*Ox + Bx*Hx*Ox) {
        int t = idx - Bx*Hx*Ox*Ox;
        int bh = t >> 6, e = t & 63;
        float s = z[t];
        #pragma unroll
        for (int c = 0; c < 8; c++) s += g_zpart[((size_t)bh*8 + c)*64 + e];
        dout[OUT_Z_OFF + t] = s;
    }
}

// ---------------------------------------------------------------------------
extern "C" void kernel_launch(void* const* d_in, const int* in_sizes, int n_in,
                              void* d_out, int out_size) {
    const float* inp  = (const float*)d_in[0];
    const float* mem  = (const float*)d_in[1];
    const float* z    = (const float*)d_in[2];
    const float* Wqkv = (const float*)d_in[3];
    const float* Wout = (const float*)d_in[4];
    const float* beta = (const float*)d_in[5];
    float* out = (float*)d_out;

    cudaFuncSetAttribute(gemm_qkv_mma, cudaFuncAttributeMaxDynamicSharedMemorySize,
                         QKV_SMEM_BYTES);
    cudaFuncSetAttribute(flash_mma, cudaFuncAttributeMaxDynamicSharedMemorySize,
                         FLASH_SMEM);
    cudaFuncSetAttribute(amem_mma, cudaFuncAttributeMaxDynamicSharedMemorySize,
                         AMEM_SMEM);

    TSArr ts;
    for (int i = 0; i < Dx; i++)
        ts.v[i] = (float)exp(log(1e-3) * (double)(2*(i/2)) / (double)Dx);

    // Legal capture topology: side stream first WAITS on an event recorded in
    // the origin stream, then runs wprep concurrent with xfuse.
    cudaEventRecord(g_ss.e_start, 0);
    cudaStreamWaitEvent(g_ss.s, g_ss.e_start, 0);

    wprep_kernel<<<WT_BLOCKS + PW_BLOCKS, 256, 0, g_ss.s>>>(Wqkv, Wout);       // side
    xfuse_kernel<<<Nx*Dx/2/256, 256>>>(ts, inp);                               // main

    cudaEventRecord(g_ss.e_wjoin, g_ss.s);
    cudaStreamWaitEvent(0, g_ss.e_wjoin, 0);

    gemm_qkv_mma<<<dim3(QKVCOLS/128, ROWS/128), 512, QKV_SMEM_BYTES>>>(0);     // main

    cudaEventRecord(g_ss.e_fork, 0);
    cudaStreamWaitEvent(g_ss.s, g_ss.e_fork, 0);

    flash_mma<<<dim3(Nx/64, Bx*Hx), 128, FLASH_SMEM>>>();                      // main (profiled)
    amem_mma<<<dim3(Nx/128, Bx*Hx), 128, AMEM_SMEM, g_ss.s>>>(mem, z);         // side
    update_kernel<<<dim3(8, Bx*Hx), 256, 0, g_ss.s>>>();                       // side
    reduce_kernel<<<(Bx*Hx*Ox*Ox + Bx*Hx*Ox + 255)/256, 256, 0, g_ss.s>>>(mem, z, out); // side

    cudaEventRecord(g_ss.e_join, g_ss.s);
    cudaStreamWaitEvent(0, g_ss.e_join, 0);

    gemm_proj<<<ROWS/64, 256>>>(beta, out);                                    // main
}